// round 15
// baseline (speedup 1.0000x reference)
#include <cuda_runtime.h>
#include <cuda_fp16.h>
#include <math.h>
#include <stdint.h>

#define N_NODES 8192
#define D_DIM   512
#define E_EDGES 262144
#define BUCKET  128

// Scratch (allocation-free rule: device globals)
__device__ float g_bufA[N_NODES * D_DIM];  // layer-2 output / emb (f32)
__device__ float g_bufC[N_NODES * D_DIM];  // layer-1 output (f32)
__device__ __half g_y[N_NODES * D_DIM];    // fp16 pre-scaled gather source
__device__ float g_rowsum[N_NODES];        // fused rowsum accumulator
__device__ __half g_hi[N_NODES * D_DIM];   // fp16 hi (lin X) / fp16 emb (sim)
__device__ __half g_lo[N_NODES * D_DIM];   // fp16 lo (lin X)
__device__ __half g_Whi[D_DIM * D_DIM];    // W fp16 hi
__device__ __half g_Wlo[D_DIM * D_DIM];    // W fp16 lo (residual)
// bucketed CSR scratch
__device__ int   g_cnt[N_NODES];
__device__ int   g_csr_src[N_NODES * BUCKET];
__device__ float g_csr_w[N_NODES * BUCKET];

// ============================ PTX helpers (base PTX only!) =================
__device__ __forceinline__ uint32_t smem_u32(const void* p) {
    uint32_t a;
    asm("{ .reg .u64 t; cvta.to.shared.u64 t, %1; cvt.u32.u64 %0, t; }"
        : "=r"(a) : "l"(p));
    return a;
}
#define CPA16(s, g) \
    asm volatile("cp.async.cg.shared.global [%0], [%1], 16;" :: "r"(s), "l"(g))
#define CPA_COMMIT() asm volatile("cp.async.commit_group;" ::: "memory")

__device__ __forceinline__ void ldm_x4(uint32_t* r, uint32_t addr) {
    asm volatile("ldmatrix.sync.aligned.m8n8.x4.shared.b16 {%0,%1,%2,%3}, [%4];"
                 : "=r"(r[0]), "=r"(r[1]), "=r"(r[2]), "=r"(r[3]) : "r"(addr));
}
__device__ __forceinline__ void mma_fp16(float* c, const uint32_t* a,
                                         const uint32_t* b) {
    asm volatile(
        "mma.sync.aligned.m16n8k16.row.col.f32.f16.f16.f32 "
        "{%0,%1,%2,%3}, {%4,%5,%6,%7}, {%8,%9}, {%0,%1,%2,%3};"
        : "+f"(c[0]), "+f"(c[1]), "+f"(c[2]), "+f"(c[3])
        : "r"(a[0]), "r"(a[1]), "r"(a[2]), "r"(a[3]), "r"(b[0]), "r"(b[1]));
}

// ============================ small kernels ================================
// rowsum -> y = x * (1/(rowsum+1e-4)) in fp16 (rounded AFTER amplification)
__global__ void rowsum_inv_y_kernel(const float* __restrict__ x,
                                    __half* __restrict__ y) {
    int row = blockIdx.x;
    const float4 v = reinterpret_cast<const float4*>(x)[row * (D_DIM / 4) + threadIdx.x];
    float s = v.x + v.y + v.z + v.w;
    #pragma unroll
    for (int o = 16; o > 0; o >>= 1) s += __shfl_down_sync(0xffffffffu, s, o);
    __shared__ float red[4];
    __shared__ float sinv;
    if ((threadIdx.x & 31) == 0) red[threadIdx.x >> 5] = s;
    __syncthreads();
    if (threadIdx.x == 0) {
        float t = red[0] + red[1] + red[2] + red[3];
        sinv = 1.0f / (t + 1e-4f);
    }
    __syncthreads();
    float iv = sinv;
    int i = row * (D_DIM / 4) + threadIdx.x;
    reinterpret_cast<__half2*>(y)[i * 2]     = __floats2half2_rn(v.x * iv, v.y * iv);
    reinterpret_cast<__half2*>(y)[i * 2 + 1] = __floats2half2_rn(v.z * iv, v.w * iv);
}

// y = C * (1/(rowsum[row]+1e-4)) in fp16 (layer-2 message payload)
__global__ void scale_y_kernel(const float* __restrict__ C,
                               const float* __restrict__ rowsum,
                               __half* __restrict__ y) {
    int row = blockIdx.x;
    float iv = 1.0f / (rowsum[row] + 1e-4f);
    const float4 v = reinterpret_cast<const float4*>(C)[row * (D_DIM / 4) + threadIdx.x];
    int i = row * (D_DIM / 4) + threadIdx.x;
    reinterpret_cast<__half2*>(y)[i * 2]     = __floats2half2_rn(v.x * iv, v.y * iv);
    reinterpret_cast<__half2*>(y)[i * 2 + 1] = __floats2half2_rn(v.z * iv, v.w * iv);
}

__global__ void zero2_kernel(int* __restrict__ cnt, float* __restrict__ rowsum) {
    int i = blockIdx.x * blockDim.x + threadIdx.x;
    if (i < N_NODES) { cnt[i] = 0; rowsum[i] = 0.f; }
}

// W (f32) -> fp16 hi + fp16 lo residual, 4 elements/thread
__global__ void wsplit_kernel(const float* __restrict__ W,
                              __half* __restrict__ Whi, __half* __restrict__ Wlo,
                              int n4) {
    for (int i = blockIdx.x * blockDim.x + threadIdx.x; i < n4; i += gridDim.x * blockDim.x) {
        float4 v = reinterpret_cast<const float4*>(W)[i];
        float a[4] = {v.x, v.y, v.z, v.w};
        __half h[4], l[4];
        #pragma unroll
        for (int q = 0; q < 4; q++) {
            h[q] = __float2half_rn(a[q]);
            l[q] = __float2half_rn(a[q] - __half2float(h[q]));
        }
        reinterpret_cast<__half2*>(Whi)[i * 2]     = __halves2half2(h[0], h[1]);
        reinterpret_cast<__half2*>(Whi)[i * 2 + 1] = __halves2half2(h[2], h[3]);
        reinterpret_cast<__half2*>(Wlo)[i * 2]     = __halves2half2(l[0], l[1]);
        reinterpret_cast<__half2*>(Wlo)[i * 2 + 1] = __halves2half2(l[2], l[3]);
    }
}

// ================== bucketed CSR build: one pass over edges ================
__global__ void fill_bucket_kernel(const int* __restrict__ ei,
                                   const float* __restrict__ ew,
                                   int* __restrict__ cnt,
                                   int* __restrict__ csr_src,
                                   float* __restrict__ csr_w) {
    int e = blockIdx.x * blockDim.x + threadIdx.x;
    if (e >= E_EDGES) return;
    int dst = ei[e];
    int pos = atomicAdd(&cnt[dst], 1);
    if (pos < BUCKET) {
        csr_src[dst * BUCKET + pos] = ei[E_EDGES + e];
        csr_w[dst * BUCKET + pos] = ew[e];
    }
}

// == bucket SpMM (fp16 gather, smem-staged indices) + fused fp16 hi/lo split =
__global__ __launch_bounds__(128)
void spmm_csr_kernel(const __half* __restrict__ y,
                     const int* __restrict__ cnt,
                     const int* __restrict__ csr_src, const float* __restrict__ csr_w,
                     __half* __restrict__ hi, __half* __restrict__ lo) {
    __shared__ int   s_src[BUCKET];
    __shared__ float s_w[BUCKET];
    int row = blockIdx.x;
    int t = threadIdx.x;
    int n = min(cnt[row], BUCKET);
    float acc[4] = {0.f, 0.f, 0.f, 0.f};

    if (t < n) {
        s_src[t] = csr_src[row * BUCKET + t];
        s_w[t] = csr_w[row * BUCKET + t];
    }
    __syncthreads();

    int j = 0;
    for (; j + 8 <= n; j += 8) {
        int idx8[8]; float w8[8]; uint2 p8[8];
        #pragma unroll
        for (int q = 0; q < 8; q++) { idx8[q] = s_src[j + q]; w8[q] = s_w[j + q]; }
        #pragma unroll
        for (int q = 0; q < 8; q++)
            p8[q] = __ldg(reinterpret_cast<const uint2*>(y) + idx8[q] * (D_DIM / 4) + t);
        #pragma unroll
        for (int q = 0; q < 8; q++) {
            float2 f;
            f = __half22float2(*reinterpret_cast<__half2*>(&p8[q].x));
            acc[0] = fmaf(w8[q], f.x, acc[0]); acc[1] = fmaf(w8[q], f.y, acc[1]);
            f = __half22float2(*reinterpret_cast<__half2*>(&p8[q].y));
            acc[2] = fmaf(w8[q], f.x, acc[2]); acc[3] = fmaf(w8[q], f.y, acc[3]);
        }
    }
    for (; j < n; j++) {
        int src = s_src[j];
        float w = s_w[j];
        uint2 p = __ldg(reinterpret_cast<const uint2*>(y) + src * (D_DIM / 4) + t);
        float2 f;
        f = __half22float2(*reinterpret_cast<__half2*>(&p.x));
        acc[0] = fmaf(w, f.x, acc[0]); acc[1] = fmaf(w, f.y, acc[1]);
        f = __half22float2(*reinterpret_cast<__half2*>(&p.y));
        acc[2] = fmaf(w, f.x, acc[2]); acc[3] = fmaf(w, f.y, acc[3]);
    }

    // fp16 hi/lo split of the f32 accumulator
    uint16_t h[4], l[4];
    #pragma unroll
    for (int q = 0; q < 4; q++) {
        __half hb = __float2half_rn(acc[q]);
        __half lb = __float2half_rn(acc[q] - __half2float(hb));
        h[q] = *reinterpret_cast<uint16_t*>(&hb);
        l[q] = *reinterpret_cast<uint16_t*>(&lb);
    }
    int i = row * (D_DIM / 4) + t;
    reinterpret_cast<uint2*>(hi)[i] =
        make_uint2(((uint32_t)h[1] << 16) | h[0], ((uint32_t)h[3] << 16) | h[2]);
    reinterpret_cast<uint2*>(lo)[i] =
        make_uint2(((uint32_t)l[1] << 16) | l[0], ((uint32_t)l[3] << 16) | l[2]);
}

// L2 normalize rows of x and emit fp16
__global__ void l2norm_f16_kernel(const float* __restrict__ x,
                                  __half* __restrict__ emb) {
    int row = blockIdx.x;
    const float4 v = reinterpret_cast<const float4*>(x)[row * (D_DIM / 4) + threadIdx.x];
    float s = v.x * v.x + v.y * v.y + v.z * v.z + v.w * v.w;
    #pragma unroll
    for (int o = 16; o > 0; o >>= 1) s += __shfl_down_sync(0xffffffffu, s, o);
    __shared__ float red[4];
    __shared__ float sscale;
    if ((threadIdx.x & 31) == 0) red[threadIdx.x >> 5] = s;
    __syncthreads();
    if (threadIdx.x == 0) {
        float t = red[0] + red[1] + red[2] + red[3];
        sscale = 1.0f / fmaxf(sqrtf(t), 1e-12f);
    }
    __syncthreads();
    float sc = sscale;
    int i = row * (D_DIM / 4) + threadIdx.x;
    reinterpret_cast<__half2*>(emb)[i * 2]     = __floats2half2_rn(v.x * sc, v.y * sc);
    reinterpret_cast<__half2*>(emb)[i * 2 + 1] = __floats2half2_rn(v.z * sc, v.w * sc);
}

// ==================== shared mma tile machinery (128x128) ==================
#define SIM_BM 128
#define SIM_KC 32
#define ROWB   80
#define OPSZ   (SIM_BM * ROWB)          // 10240 B
#define LIN_STG2 (3 * OPSZ)             // Xhi, Xlo, Whi: 30720 B
#define LIN_STG3 (4 * OPSZ)             // + Wlo: 40960 B
#define LIN_SMEM2 (2 * LIN_STG2)        // 61440 B
#define LIN_SMEM3 (2 * LIN_STG3)        // 81920 B
#define SIM_STG  (2 * OPSZ)             // 20480 B
#define SIM_NSTG 3
#define SIM_SMEM_TOT (SIM_BM * 129 * 4) // 66048 B (>= 3*SIM_STG = 61440)
#define NCHUNK (D_DIM / SIM_KC)

struct MmaCtx { float acc[4][4][4]; };

// fp16 lin mainloop: acc = (Xhi+Xlo) x Whi^T [+ Xhi x Wlo^T if NT==3], 2-stage
// 256 threads, 8 warps (2x4), warp tile 64x32
template <int NT>
__device__ __forceinline__ void mma_mainloop_lin(
    const __half* gA0, const __half* gA1,
    const __half* gB0, const __half* gB1,
    uint32_t sb, int tid, int wm, int wn, int lane, MmaCtx& cx) {

    const int STG = (NT == 3) ? LIN_STG3 : LIN_STG2;

    #pragma unroll
    for (int i = 0; i < 4; i++)
        #pragma unroll
        for (int j = 0; j < 4; j++)
            #pragma unroll
            for (int q = 0; q < 4; q++) cx.acc[i][j][q] = 0.f;

    const __half* gA[2] = {gA0, gA1};

    auto load_chunk = [&](int c) {
        uint32_t st = sb + (uint32_t)(c & 1) * STG;
        int koff = c * SIM_KC;
        #pragma unroll
        for (int i = 0; i < 2; i++) {
            int idx = i * 256 + tid;
            int r = idx >> 2, cc = idx & 3;
            #pragma unroll
            for (int h = 0; h < 2; h++)
                CPA16(st + h * OPSZ + r * ROWB + cc * 16,
                      gA[h] + (size_t)r * D_DIM + koff + cc * 8);
            CPA16(st + 2 * OPSZ + r * ROWB + cc * 16,
                  gB0 + (size_t)r * D_DIM + koff + cc * 8);
            if (NT == 3)
                CPA16(st + 3 * OPSZ + r * ROWB + cc * 16,
                      gB1 + (size_t)r * D_DIM + koff + cc * 8);
        }
        CPA_COMMIT();
    };

    load_chunk(0);
    load_chunk(1);

    for (int c = 0; c < NCHUNK; c++) {
        if (c < NCHUNK - 1) asm volatile("cp.async.wait_group 1;" ::: "memory");
        else                asm volatile("cp.async.wait_group 0;" ::: "memory");
        __syncthreads();

        uint32_t st = sb + (uint32_t)(c & 1) * STG;
        #pragma unroll
        for (int ks = 0; ks < 2; ks++) {
            uint32_t afr[2][4][4];
            {
                int rowA = wm * 64 + (lane & 15);
                int chk = 2 * ks + (lane >> 4);
                uint32_t off = (uint32_t)(rowA * ROWB + chk * 16);
                #pragma unroll
                for (int h = 0; h < 2; h++)
                    #pragma unroll
                    for (int mi = 0; mi < 4; mi++)
                        ldm_x4(afr[h][mi], st + h * OPSZ + off + (uint32_t)(mi * 16 * ROWB));
            }
            uint32_t bfr[4][2], cfr[4][2];
            {
                int rowB = wn * 32 + ((lane >> 4) & 1) * 8 + (lane & 7);
                int chk = 2 * ks + ((lane >> 3) & 1);
                uint32_t off = (uint32_t)(rowB * ROWB + chk * 16);
                #pragma unroll
                for (int jp = 0; jp < 2; jp++) {
                    uint32_t r4[4];
                    ldm_x4(r4, st + 2 * OPSZ + off + (uint32_t)(jp * 16 * ROWB));
                    bfr[jp * 2 + 0][0] = r4[0]; bfr[jp * 2 + 0][1] = r4[1];
                    bfr[jp * 2 + 1][0] = r4[2]; bfr[jp * 2 + 1][1] = r4[3];
                    if (NT == 3) {
                        ldm_x4(r4, st + 3 * OPSZ + off + (uint32_t)(jp * 16 * ROWB));
                        cfr[jp * 2 + 0][0] = r4[0]; cfr[jp * 2 + 0][1] = r4[1];
                        cfr[jp * 2 + 1][0] = r4[2]; cfr[jp * 2 + 1][1] = r4[3];
                    }
                }
            }
            #pragma unroll
            for (int mi = 0; mi < 4; mi++)
                #pragma unroll
                for (int nj = 0; nj < 4; nj++) {
                    mma_fp16(cx.acc[mi][nj], afr[0][mi], bfr[nj]);      // Xhi*Whi
                    mma_fp16(cx.acc[mi][nj], afr[1][mi], bfr[nj]);      // Xlo*Whi
                    if (NT == 3)
                        mma_fp16(cx.acc[mi][nj], afr[0][mi], cfr[nj]);  // Xhi*Wlo
                }
        }
        __syncthreads();
        if (c + 2 < NCHUNK) load_chunk(c + 2);
    }
}

// ==================== linear layer: elu(X @ W^T + b) [+ rowsum] ============
template <int NT>
__global__ __launch_bounds__(256, 2)
void lin_mma_kernel(const __half* __restrict__ Xhi,
                    const __half* __restrict__ Xlo,
                    const __half* __restrict__ Whi,
                    const __half* __restrict__ Wlo,
                    const float* __restrict__ bias,
                    float* __restrict__ Cout,
                    float* __restrict__ rowsum) {
    extern __shared__ char smem[];
    const uint32_t sb = smem_u32(smem);
    const int tid = threadIdx.x;
    const int wid = tid >> 5, lane = tid & 31;
    const int wm = wid >> 2, wn = wid & 3;
    const int row0 = blockIdx.y * SIM_BM, col0 = blockIdx.x * SIM_BM;

    MmaCtx cx;
    mma_mainloop_lin<NT>(Xhi + (size_t)row0 * D_DIM, Xlo + (size_t)row0 * D_DIM,
                         Whi + (size_t)col0 * D_DIM, Wlo + (size_t)col0 * D_DIM,
                         sb, tid, wm, wn, lane, cx);

    #pragma unroll
    for (int mi = 0; mi < 4; mi++) {
        int r = row0 + wm * 64 + mi * 16 + (lane >> 2);
        float rs0 = 0.f, rs1 = 0.f;
        #pragma unroll
        for (int nj = 0; nj < 4; nj++) {
            int c = col0 + wn * 32 + nj * 8 + (lane & 3) * 2;
            float b0 = bias[c], b1 = bias[c + 1];
            float z0 = cx.acc[mi][nj][0] + b0, z1 = cx.acc[mi][nj][1] + b1;
            float z2 = cx.acc[mi][nj][2] + b0, z3 = cx.acc[mi][nj][3] + b1;
            z0 = (z0 > 0.f) ? z0 : expm1f(z0);
            z1 = (z1 > 0.f) ? z1 : expm1f(z1);
            z2 = (z2 > 0.f) ? z2 : expm1f(z2);
            z3 = (z3 > 0.f) ? z3 : expm1f(z3);
            rs0 += z0 + z1;
            rs1 += z2 + z3;
            *reinterpret_cast<float2*>(Cout + (size_t)r * D_DIM + c) = make_float2(z0, z1);
            *reinterpret_cast<float2*>(Cout + (size_t)(r + 8) * D_DIM + c) = make_float2(z2, z3);
        }
        if (rowsum) {
            rs0 += __shfl_xor_sync(0xffffffffu, rs0, 1);
            rs0 += __shfl_xor_sync(0xffffffffu, rs0, 2);
            rs1 += __shfl_xor_sync(0xffffffffu, rs1, 1);
            rs1 += __shfl_xor_sync(0xffffffffu, rs1, 2);
            if ((lane & 3) == 0) {
                atomicAdd(rowsum + r, rs0);
                atomicAdd(rowsum + r + 8, rs1);
            }
        }
    }
}

// ==================== similarity: relu(emb @ emb^T), symmetric =============
// 128 threads = 4 warps (2x2), warp tile 64x64, 3-stage pipeline.
__global__ __launch_bounds__(128, 2)
void sim_mma_kernel(const __half* __restrict__ emb,
                    float* __restrict__ out) {
    extern __shared__ char smem[];
    const uint32_t sb = smem_u32(smem);
    const int tid = threadIdx.x;
    const int wid = tid >> 5, lane = tid & 31;
    const int wm = wid >> 1, wn = wid & 1;   // 2x2 warp grid

    int k = blockIdx.x;
    int bi = (int)((sqrtf(8.f * (float)k + 1.f) - 1.f) * 0.5f);
    while ((bi + 1) * (bi + 2) / 2 <= k) bi++;
    while (bi * (bi + 1) / 2 > k) bi--;
    int bj = k - bi * (bi + 1) / 2;
    const int row0 = bi * SIM_BM, col0 = bj * SIM_BM;

    const __half* gA0 = emb + (size_t)row0 * D_DIM;
    const __half* gB0 = emb + (size_t)col0 * D_DIM;

    float acc[4][8][4];
    #pragma unroll
    for (int i = 0; i < 4; i++)
        #pragma unroll
        for (int j = 0; j < 8; j++)
            #pragma unroll
            for (int q = 0; q < 4; q++) acc[i][j][q] = 0.f;

    auto load_chunk = [&](int c) {
        uint32_t st = sb + (uint32_t)(c % SIM_NSTG) * SIM_STG;
        int koff = c * SIM_KC;
        #pragma unroll
        for (int i = 0; i < 4; i++) {
            int idx = i * 128 + tid;
            int r = idx >> 2, cc = idx & 3;
            CPA16(st + r * ROWB + cc * 16,
                  gA0 + (size_t)r * D_DIM + koff + cc * 8);
            CPA16(st + OPSZ + r * ROWB + cc * 16,
                  gB0 + (size_t)r * D_DIM + koff + cc * 8);
        }
        CPA_COMMIT();
    };

    load_chunk(0);
    load_chunk(1);
    load_chunk(2);

    for (int c = 0; c < NCHUNK; c++) {
        if (c + 2 < NCHUNK)      asm volatile("cp.async.wait_group 2;" ::: "memory");
        else if (c + 1 < NCHUNK) asm volatile("cp.async.wait_group 1;" ::: "memory");
        else                     asm volatile("cp.async.wait_group 0;" ::: "memory");
        __syncthreads();

        uint32_t st = sb + (uint32_t)(c % SIM_NSTG) * SIM_STG;
        #pragma unroll
        for (int ks = 0; ks < 2; ks++) {
            uint32_t afr[4][4];
            {
                int rowA = wm * 64 + (lane & 15);
                int chk = 2 * ks + (lane >> 4);
                uint32_t off = (uint32_t)(rowA * ROWB + chk * 16);
                #pragma unroll
                for (int mi = 0; mi < 4; mi++)
                    ldm_x4(afr[mi], st + off + (uint32_t)(mi * 16 * ROWB));
            }
            uint32_t bfr[8][2];
            {
                int rowB = wn * 64 + ((lane >> 4) & 1) * 8 + (lane & 7);
                int chk = 2 * ks + ((lane >> 3) & 1);
                uint32_t off = (uint32_t)(rowB * ROWB + chk * 16);
                #pragma unroll
                for (int jp = 0; jp < 4; jp++) {
                    uint32_t r4[4];
                    ldm_x4(r4, st + OPSZ + off + (uint32_t)(jp * 16 * ROWB));
                    bfr[jp * 2 + 0][0] = r4[0]; bfr[jp * 2 + 0][1] = r4[1];
                    bfr[jp * 2 + 1][0] = r4[2]; bfr[jp * 2 + 1][1] = r4[3];
                }
            }
            #pragma unroll
            for (int mi = 0; mi < 4; mi++)
                #pragma unroll
                for (int nj = 0; nj < 8; nj++)
                    mma_fp16(acc[mi][nj], afr[mi], bfr[nj]);
        }
        __syncthreads();
        if (c + 3 < NCHUNK) load_chunk(c + 3);
    }

    // -------- epilogue: acc -> padded smem -> relu -> out (+ mirror) --------
    __syncthreads();
    float* Csm = reinterpret_cast<float*>(smem);   // 128 x 129 floats
    #pragma unroll
    for (int mi = 0; mi < 4; mi++) {
        int r = wm * 64 + mi * 16 + (lane >> 2);
        #pragma unroll
        for (int nj = 0; nj < 8; nj++) {
            int cc = wn * 64 + nj * 8 + (lane & 3) * 2;
            float z0 = acc[mi][nj][0], z1 = acc[mi][nj][1];
            float z2 = acc[mi][nj][2], z3 = acc[mi][nj][3];
            Csm[r * 129 + cc]           = (z0 > 0.f) ? z0 : 0.f;
            Csm[r * 129 + cc + 1]       = (z1 > 0.f) ? z1 : 0.f;
            Csm[(r + 8) * 129 + cc]     = (z2 > 0.f) ? z2 : 0.f;
            Csm[(r + 8) * 129 + cc + 1] = (z3 > 0.f) ? z3 : 0.f;
        }
    }
    __syncthreads();

    #pragma unroll 4
    for (int r = 0; r < 128; r++)
        out[(size_t)(row0 + r) * N_NODES + col0 + tid] = Csm[r * 129 + tid];

    if (bi != bj) {
        #pragma unroll 4
        for (int i = 0; i < 128; i++) {
            int idx = i * 128 + tid;
            int rr = idx & 127, cc = idx >> 7;
            out[(size_t)(col0 + cc) * N_NODES + row0 + rr] = Csm[rr * 129 + cc];
        }
    }
}

// ===========================================================================
extern "C" void kernel_launch(void* const* d_in, const int* in_sizes, int n_in,
                              void* d_out, int out_size) {
    const float* x  = (const float*)d_in[0];
    const int*   ei = (const int*)d_in[1];
    const float* ew = (const float*)d_in[2];
    const float* W  = (const float*)d_in[3];
    const float* b  = (const float*)d_in[4];
    float* out = (float*)d_out;

    float *A, *C, *rowsum, *csr_w;
    __half *y, *hi, *lo, *Whi, *Wlo;
    int *cnt, *csr_src;
    cudaGetSymbolAddress((void**)&A, g_bufA);
    cudaGetSymbolAddress((void**)&C, g_bufC);
    cudaGetSymbolAddress((void**)&y, g_y);
    cudaGetSymbolAddress((void**)&rowsum, g_rowsum);
    cudaGetSymbolAddress((void**)&hi, g_hi);
    cudaGetSymbolAddress((void**)&lo, g_lo);
    cudaGetSymbolAddress((void**)&Whi, g_Whi);
    cudaGetSymbolAddress((void**)&Wlo, g_Wlo);
    cudaGetSymbolAddress((void**)&cnt, g_cnt);
    cudaGetSymbolAddress((void**)&csr_src, g_csr_src);
    cudaGetSymbolAddress((void**)&csr_w, g_csr_w);

    cudaFuncSetAttribute(sim_mma_kernel,
                         cudaFuncAttributeMaxDynamicSharedMemorySize, SIM_SMEM_TOT);
    cudaFuncSetAttribute(lin_mma_kernel<3>,
                         cudaFuncAttributeMaxDynamicSharedMemorySize, LIN_SMEM3);
    cudaFuncSetAttribute(lin_mma_kernel<2>,
                         cudaFuncAttributeMaxDynamicSharedMemorySize, LIN_SMEM2);

    dim3 gLin(D_DIM / SIM_BM, N_NODES / SIM_BM);   // 4 x 64

    // ---- one-time per launch: zero, W split, bucketed CSR (one pass) ----
    zero2_kernel<<<N_NODES / 256, 256>>>(cnt, rowsum);
    wsplit_kernel<<<128, 256>>>(W, Whi, Wlo, D_DIM * D_DIM / 4);
    fill_bucket_kernel<<<E_EDGES / 512, 512>>>(ei, ew, cnt, csr_src, csr_w);

    // ---- layer 1: y = x*inv (fp16), gather y, lin 3-term (+fused rowsum) --
    rowsum_inv_y_kernel<<<N_NODES, 128>>>(x, y);
    spmm_csr_kernel<<<N_NODES, 128>>>(y, cnt, csr_src, csr_w, hi, lo);
    lin_mma_kernel<3><<<gLin, 256, LIN_SMEM3>>>(hi, lo, Whi, Wlo, b, C, rowsum);

    // ---- layer 2: y = C*inv (fp16), gather y, lin 2-term ----
    scale_y_kernel<<<N_NODES, 128>>>(C, rowsum, y);
    spmm_csr_kernel<<<N_NODES, 128>>>(y, cnt, csr_src, csr_w, hi, lo);
    lin_mma_kernel<2><<<gLin, 256, LIN_SMEM2>>>(hi, lo, Whi, Wlo, b, A, nullptr);

    // ---- normalize -> fp16 emb (reuse hi buffer) ----
    l2norm_f16_kernel<<<N_NODES, 128>>>(A, hi);

    // ---- similarity: symmetric tiles, pure fp16 + relu, 64x64 warp tiles --
    int nblk = (N_NODES / SIM_BM);             // 64
    int ntri = nblk * (nblk + 1) / 2;          // 2080
    sim_mma_kernel<<<ntri, 128, SIM_SMEM_TOT>>>(hi, out);
}

// round 16
// speedup vs baseline: 1.0439x; 1.0439x over previous
#include <cuda_runtime.h>
#include <cuda_fp16.h>
#include <math.h>
#include <stdint.h>

#define N_NODES 8192
#define D_DIM   512
#define E_EDGES 262144
#define BUCKET  128

// Scratch (allocation-free rule: device globals)
__device__ float g_bufA[N_NODES * D_DIM];  // layer-2 output / emb (f32)
__device__ float g_bufC[N_NODES * D_DIM];  // layer-1 output (f32)
__device__ __half g_y[N_NODES * D_DIM];    // fp16 pre-scaled gather source
__device__ float g_rowsum[N_NODES];        // fused rowsum accumulator
__device__ __half g_hi[N_NODES * D_DIM];   // fp16 hi (lin X) / fp16 emb (sim)
__device__ __half g_lo[N_NODES * D_DIM];   // fp16 lo (lin X)
__device__ __half g_Whi[D_DIM * D_DIM];    // W fp16 hi
__device__ __half g_Wlo[D_DIM * D_DIM];    // W fp16 lo (residual)
// bucketed CSR scratch
__device__ int   g_cnt[N_NODES];
__device__ int   g_csr_src[N_NODES * BUCKET];
__device__ float g_csr_w[N_NODES * BUCKET];

// ============================ PTX helpers (base PTX only!) =================
__device__ __forceinline__ uint32_t smem_u32(const void* p) {
    uint32_t a;
    asm("{ .reg .u64 t; cvta.to.shared.u64 t, %1; cvt.u32.u64 %0, t; }"
        : "=r"(a) : "l"(p));
    return a;
}
#define CPA16(s, g) \
    asm volatile("cp.async.cg.shared.global [%0], [%1], 16;" :: "r"(s), "l"(g))
#define CPA_COMMIT() asm volatile("cp.async.commit_group;" ::: "memory")

__device__ __forceinline__ void ldm_x4(uint32_t* r, uint32_t addr) {
    asm volatile("ldmatrix.sync.aligned.m8n8.x4.shared.b16 {%0,%1,%2,%3}, [%4];"
                 : "=r"(r[0]), "=r"(r[1]), "=r"(r[2]), "=r"(r[3]) : "r"(addr));
}
__device__ __forceinline__ void mma_fp16(float* c, const uint32_t* a,
                                         const uint32_t* b) {
    asm volatile(
        "mma.sync.aligned.m16n8k16.row.col.f32.f16.f16.f32 "
        "{%0,%1,%2,%3}, {%4,%5,%6,%7}, {%8,%9}, {%0,%1,%2,%3};"
        : "+f"(c[0]), "+f"(c[1]), "+f"(c[2]), "+f"(c[3])
        : "r"(a[0]), "r"(a[1]), "r"(a[2]), "r"(a[3]), "r"(b[0]), "r"(b[1]));
}

// ============================ small kernels ================================
// rowsum -> y = x * (1/(rowsum+1e-4)) in fp16 (rounded AFTER amplification)
__global__ void rowsum_inv_y_kernel(const float* __restrict__ x,
                                    __half* __restrict__ y) {
    int row = blockIdx.x;
    const float4 v = reinterpret_cast<const float4*>(x)[row * (D_DIM / 4) + threadIdx.x];
    float s = v.x + v.y + v.z + v.w;
    #pragma unroll
    for (int o = 16; o > 0; o >>= 1) s += __shfl_down_sync(0xffffffffu, s, o);
    __shared__ float red[4];
    __shared__ float sinv;
    if ((threadIdx.x & 31) == 0) red[threadIdx.x >> 5] = s;
    __syncthreads();
    if (threadIdx.x == 0) {
        float t = red[0] + red[1] + red[2] + red[3];
        sinv = 1.0f / (t + 1e-4f);
    }
    __syncthreads();
    float iv = sinv;
    int i = row * (D_DIM / 4) + threadIdx.x;
    reinterpret_cast<__half2*>(y)[i * 2]     = __floats2half2_rn(v.x * iv, v.y * iv);
    reinterpret_cast<__half2*>(y)[i * 2 + 1] = __floats2half2_rn(v.z * iv, v.w * iv);
}

// y = C * (1/(rowsum[row]+1e-4)) in fp16 (layer-2 message payload)
__global__ void scale_y_kernel(const float* __restrict__ C,
                               const float* __restrict__ rowsum,
                               __half* __restrict__ y) {
    int row = blockIdx.x;
    float iv = 1.0f / (rowsum[row] + 1e-4f);
    const float4 v = reinterpret_cast<const float4*>(C)[row * (D_DIM / 4) + threadIdx.x];
    int i = row * (D_DIM / 4) + threadIdx.x;
    reinterpret_cast<__half2*>(y)[i * 2]     = __floats2half2_rn(v.x * iv, v.y * iv);
    reinterpret_cast<__half2*>(y)[i * 2 + 1] = __floats2half2_rn(v.z * iv, v.w * iv);
}

__global__ void zero2_kernel(int* __restrict__ cnt, float* __restrict__ rowsum) {
    int i = blockIdx.x * blockDim.x + threadIdx.x;
    if (i < N_NODES) { cnt[i] = 0; rowsum[i] = 0.f; }
}

// W (f32) -> fp16 hi + fp16 lo residual, 4 elements/thread
__global__ void wsplit_kernel(const float* __restrict__ W,
                              __half* __restrict__ Whi, __half* __restrict__ Wlo,
                              int n4) {
    for (int i = blockIdx.x * blockDim.x + threadIdx.x; i < n4; i += gridDim.x * blockDim.x) {
        float4 v = reinterpret_cast<const float4*>(W)[i];
        float a[4] = {v.x, v.y, v.z, v.w};
        __half h[4], l[4];
        #pragma unroll
        for (int q = 0; q < 4; q++) {
            h[q] = __float2half_rn(a[q]);
            l[q] = __float2half_rn(a[q] - __half2float(h[q]));
        }
        reinterpret_cast<__half2*>(Whi)[i * 2]     = __halves2half2(h[0], h[1]);
        reinterpret_cast<__half2*>(Whi)[i * 2 + 1] = __halves2half2(h[2], h[3]);
        reinterpret_cast<__half2*>(Wlo)[i * 2]     = __halves2half2(l[0], l[1]);
        reinterpret_cast<__half2*>(Wlo)[i * 2 + 1] = __halves2half2(l[2], l[3]);
    }
}

// ================== bucketed CSR build: one pass over edges ================
__global__ void fill_bucket_kernel(const int* __restrict__ ei,
                                   const float* __restrict__ ew,
                                   int* __restrict__ cnt,
                                   int* __restrict__ csr_src,
                                   float* __restrict__ csr_w) {
    int e = blockIdx.x * blockDim.x + threadIdx.x;
    if (e >= E_EDGES) return;
    int dst = ei[e];
    int pos = atomicAdd(&cnt[dst], 1);
    if (pos < BUCKET) {
        csr_src[dst * BUCKET + pos] = ei[E_EDGES + e];
        csr_w[dst * BUCKET + pos] = ew[e];
    }
}

// == bucket SpMM (fp16 gather, smem-staged indices) + fused fp16 hi/lo split =
__global__ __launch_bounds__(128)
void spmm_csr_kernel(const __half* __restrict__ y,
                     const int* __restrict__ cnt,
                     const int* __restrict__ csr_src, const float* __restrict__ csr_w,
                     __half* __restrict__ hi, __half* __restrict__ lo) {
    __shared__ int   s_src[BUCKET];
    __shared__ float s_w[BUCKET];
    int row = blockIdx.x;
    int t = threadIdx.x;
    int n = min(cnt[row], BUCKET);
    float acc[4] = {0.f, 0.f, 0.f, 0.f};

    if (t < n) {
        s_src[t] = csr_src[row * BUCKET + t];
        s_w[t] = csr_w[row * BUCKET + t];
    }
    __syncthreads();

    int j = 0;
    for (; j + 8 <= n; j += 8) {
        int idx8[8]; float w8[8]; uint2 p8[8];
        #pragma unroll
        for (int q = 0; q < 8; q++) { idx8[q] = s_src[j + q]; w8[q] = s_w[j + q]; }
        #pragma unroll
        for (int q = 0; q < 8; q++)
            p8[q] = __ldg(reinterpret_cast<const uint2*>(y) + idx8[q] * (D_DIM / 4) + t);
        #pragma unroll
        for (int q = 0; q < 8; q++) {
            float2 f;
            f = __half22float2(*reinterpret_cast<__half2*>(&p8[q].x));
            acc[0] = fmaf(w8[q], f.x, acc[0]); acc[1] = fmaf(w8[q], f.y, acc[1]);
            f = __half22float2(*reinterpret_cast<__half2*>(&p8[q].y));
            acc[2] = fmaf(w8[q], f.x, acc[2]); acc[3] = fmaf(w8[q], f.y, acc[3]);
        }
    }
    for (; j < n; j++) {
        int src = s_src[j];
        float w = s_w[j];
        uint2 p = __ldg(reinterpret_cast<const uint2*>(y) + src * (D_DIM / 4) + t);
        float2 f;
        f = __half22float2(*reinterpret_cast<__half2*>(&p.x));
        acc[0] = fmaf(w, f.x, acc[0]); acc[1] = fmaf(w, f.y, acc[1]);
        f = __half22float2(*reinterpret_cast<__half2*>(&p.y));
        acc[2] = fmaf(w, f.x, acc[2]); acc[3] = fmaf(w, f.y, acc[3]);
    }

    // fp16 hi/lo split of the f32 accumulator
    uint16_t h[4], l[4];
    #pragma unroll
    for (int q = 0; q < 4; q++) {
        __half hb = __float2half_rn(acc[q]);
        __half lb = __float2half_rn(acc[q] - __half2float(hb));
        h[q] = *reinterpret_cast<uint16_t*>(&hb);
        l[q] = *reinterpret_cast<uint16_t*>(&lb);
    }
    int i = row * (D_DIM / 4) + t;
    reinterpret_cast<uint2*>(hi)[i] =
        make_uint2(((uint32_t)h[1] << 16) | h[0], ((uint32_t)h[3] << 16) | h[2]);
    reinterpret_cast<uint2*>(lo)[i] =
        make_uint2(((uint32_t)l[1] << 16) | l[0], ((uint32_t)l[3] << 16) | l[2]);
}

// L2 normalize rows of x and emit fp16
__global__ void l2norm_f16_kernel(const float* __restrict__ x,
                                  __half* __restrict__ emb) {
    int row = blockIdx.x;
    const float4 v = reinterpret_cast<const float4*>(x)[row * (D_DIM / 4) + threadIdx.x];
    float s = v.x * v.x + v.y * v.y + v.z * v.z + v.w * v.w;
    #pragma unroll
    for (int o = 16; o > 0; o >>= 1) s += __shfl_down_sync(0xffffffffu, s, o);
    __shared__ float red[4];
    __shared__ float sscale;
    if ((threadIdx.x & 31) == 0) red[threadIdx.x >> 5] = s;
    __syncthreads();
    if (threadIdx.x == 0) {
        float t = red[0] + red[1] + red[2] + red[3];
        sscale = 1.0f / fmaxf(sqrtf(t), 1e-12f);
    }
    __syncthreads();
    float sc = sscale;
    int i = row * (D_DIM / 4) + threadIdx.x;
    reinterpret_cast<__half2*>(emb)[i * 2]     = __floats2half2_rn(v.x * sc, v.y * sc);
    reinterpret_cast<__half2*>(emb)[i * 2 + 1] = __floats2half2_rn(v.z * sc, v.w * sc);
}

// ==================== shared mma tile machinery (128x128) ==================
#define SIM_BM 128
#define SIM_KC 32
#define ROWB   80
#define OPSZ   (SIM_BM * ROWB)          // 10240 B
#define LIN_STG2 (3 * OPSZ)             // Xhi, Xlo, Whi: 30720 B
#define LIN_STG3 (4 * OPSZ)             // + Wlo: 40960 B
#define LIN_SMEM2 (2 * LIN_STG2)        // 61440 B
#define LIN_SMEM3 (2 * LIN_STG3)        // 81920 B
#define SIM_STG  (2 * OPSZ)             // 20480 B
#define SIM_NSTG 3
#define SIM_SMEM_TOT (SIM_BM * 129 * 4) // 66048 B (>= 3*SIM_STG = 61440)
#define NCHUNK (D_DIM / SIM_KC)

struct MmaCtx { float acc[4][4][4]; };

// fp16 lin mainloop: acc = (Xhi+Xlo) x Whi^T [+ Xhi x Wlo^T if NT==3], 2-stage
template <int NT>
__device__ __forceinline__ void mma_mainloop_lin(
    const __half* gA0, const __half* gA1,
    const __half* gB0, const __half* gB1,
    uint32_t sb, int tid, int wm, int wn, int lane, MmaCtx& cx) {

    const int STG = (NT == 3) ? LIN_STG3 : LIN_STG2;

    #pragma unroll
    for (int i = 0; i < 4; i++)
        #pragma unroll
        for (int j = 0; j < 4; j++)
            #pragma unroll
            for (int q = 0; q < 4; q++) cx.acc[i][j][q] = 0.f;

    const __half* gA[2] = {gA0, gA1};

    auto load_chunk = [&](int c) {
        uint32_t st = sb + (uint32_t)(c & 1) * STG;
        int koff = c * SIM_KC;
        #pragma unroll
        for (int i = 0; i < 2; i++) {
            int idx = i * 256 + tid;
            int r = idx >> 2, cc = idx & 3;
            #pragma unroll
            for (int h = 0; h < 2; h++)
                CPA16(st + h * OPSZ + r * ROWB + cc * 16,
                      gA[h] + (size_t)r * D_DIM + koff + cc * 8);
            CPA16(st + 2 * OPSZ + r * ROWB + cc * 16,
                  gB0 + (size_t)r * D_DIM + koff + cc * 8);
            if (NT == 3)
                CPA16(st + 3 * OPSZ + r * ROWB + cc * 16,
                      gB1 + (size_t)r * D_DIM + koff + cc * 8);
        }
        CPA_COMMIT();
    };

    load_chunk(0);
    load_chunk(1);

    for (int c = 0; c < NCHUNK; c++) {
        if (c < NCHUNK - 1) asm volatile("cp.async.wait_group 1;" ::: "memory");
        else                asm volatile("cp.async.wait_group 0;" ::: "memory");
        __syncthreads();

        uint32_t st = sb + (uint32_t)(c & 1) * STG;
        #pragma unroll
        for (int ks = 0; ks < 2; ks++) {
            uint32_t afr[2][4][4];
            {
                int rowA = wm * 64 + (lane & 15);
                int chk = 2 * ks + (lane >> 4);
                uint32_t off = (uint32_t)(rowA * ROWB + chk * 16);
                #pragma unroll
                for (int h = 0; h < 2; h++)
                    #pragma unroll
                    for (int mi = 0; mi < 4; mi++)
                        ldm_x4(afr[h][mi], st + h * OPSZ + off + (uint32_t)(mi * 16 * ROWB));
            }
            uint32_t bfr[4][2], cfr[4][2];
            {
                int rowB = wn * 32 + ((lane >> 4) & 1) * 8 + (lane & 7);
                int chk = 2 * ks + ((lane >> 3) & 1);
                uint32_t off = (uint32_t)(rowB * ROWB + chk * 16);
                #pragma unroll
                for (int jp = 0; jp < 2; jp++) {
                    uint32_t r4[4];
                    ldm_x4(r4, st + 2 * OPSZ + off + (uint32_t)(jp * 16 * ROWB));
                    bfr[jp * 2 + 0][0] = r4[0]; bfr[jp * 2 + 0][1] = r4[1];
                    bfr[jp * 2 + 1][0] = r4[2]; bfr[jp * 2 + 1][1] = r4[3];
                    if (NT == 3) {
                        ldm_x4(r4, st + 3 * OPSZ + off + (uint32_t)(jp * 16 * ROWB));
                        cfr[jp * 2 + 0][0] = r4[0]; cfr[jp * 2 + 0][1] = r4[1];
                        cfr[jp * 2 + 1][0] = r4[2]; cfr[jp * 2 + 1][1] = r4[3];
                    }
                }
            }
            #pragma unroll
            for (int mi = 0; mi < 4; mi++)
                #pragma unroll
                for (int nj = 0; nj < 4; nj++) {
                    mma_fp16(cx.acc[mi][nj], afr[0][mi], bfr[nj]);      // Xhi*Whi
                    mma_fp16(cx.acc[mi][nj], afr[1][mi], bfr[nj]);      // Xlo*Whi
                    if (NT == 3)
                        mma_fp16(cx.acc[mi][nj], afr[0][mi], cfr[nj]);  // Xhi*Wlo
                }
        }
        __syncthreads();
        if (c + 2 < NCHUNK) load_chunk(c + 2);
    }
}

// fp16 1-term mainloop (similarity): acc = embA x embB^T, 3-stage
__device__ __forceinline__ void mma_mainloop_sim(
    const __half* gA0, const __half* gB0,
    uint32_t sb, int tid, int wm, int wn, int lane, MmaCtx& cx) {

    #pragma unroll
    for (int i = 0; i < 4; i++)
        #pragma unroll
        for (int j = 0; j < 4; j++)
            #pragma unroll
            for (int q = 0; q < 4; q++) cx.acc[i][j][q] = 0.f;

    auto load_chunk = [&](int c) {
        uint32_t st = sb + (uint32_t)(c % SIM_NSTG) * SIM_STG;
        int koff = c * SIM_KC;
        #pragma unroll
        for (int i = 0; i < 2; i++) {
            int idx = i * 256 + tid;
            int r = idx >> 2, cc = idx & 3;
            CPA16(st + r * ROWB + cc * 16,
                  gA0 + (size_t)r * D_DIM + koff + cc * 8);
            CPA16(st + OPSZ + r * ROWB + cc * 16,
                  gB0 + (size_t)r * D_DIM + koff + cc * 8);
        }
        CPA_COMMIT();
    };

    load_chunk(0);
    load_chunk(1);
    load_chunk(2);

    for (int c = 0; c < NCHUNK; c++) {
        if (c + 2 < NCHUNK)      asm volatile("cp.async.wait_group 2;" ::: "memory");
        else if (c + 1 < NCHUNK) asm volatile("cp.async.wait_group 1;" ::: "memory");
        else                     asm volatile("cp.async.wait_group 0;" ::: "memory");
        __syncthreads();

        uint32_t st = sb + (uint32_t)(c % SIM_NSTG) * SIM_STG;
        #pragma unroll
        for (int ks = 0; ks < 2; ks++) {
            uint32_t afr[4][4];
            {
                int rowA = wm * 64 + (lane & 15);
                int chk = 2 * ks + (lane >> 4);
                uint32_t off = (uint32_t)(rowA * ROWB + chk * 16);
                #pragma unroll
                for (int mi = 0; mi < 4; mi++)
                    ldm_x4(afr[mi], st + off + (uint32_t)(mi * 16 * ROWB));
            }
            uint32_t bfr[4][2];
            {
                int rowB = wn * 32 + ((lane >> 4) & 1) * 8 + (lane & 7);
                int chk = 2 * ks + ((lane >> 3) & 1);
                uint32_t off = (uint32_t)(rowB * ROWB + chk * 16);
                #pragma unroll
                for (int jp = 0; jp < 2; jp++) {
                    uint32_t r4[4];
                    ldm_x4(r4, st + OPSZ + off + (uint32_t)(jp * 16 * ROWB));
                    bfr[jp * 2 + 0][0] = r4[0]; bfr[jp * 2 + 0][1] = r4[1];
                    bfr[jp * 2 + 1][0] = r4[2]; bfr[jp * 2 + 1][1] = r4[3];
                }
            }
            #pragma unroll
            for (int mi = 0; mi < 4; mi++)
                #pragma unroll
                for (int nj = 0; nj < 4; nj++)
                    mma_fp16(cx.acc[mi][nj], afr[mi], bfr[nj]);
        }
        __syncthreads();
        if (c + 3 < NCHUNK) load_chunk(c + 3);
    }
}

// ==================== linear layer: elu(X @ W^T + b) [+ rowsum] ============
template <int NT>
__global__ __launch_bounds__(256, 2)
void lin_mma_kernel(const __half* __restrict__ Xhi,
                    const __half* __restrict__ Xlo,
                    const __half* __restrict__ Whi,
                    const __half* __restrict__ Wlo,
                    const float* __restrict__ bias,
                    float* __restrict__ Cout,
                    float* __restrict__ rowsum) {
    extern __shared__ char smem[];
    const uint32_t sb = smem_u32(smem);
    const int tid = threadIdx.x;
    const int wid = tid >> 5, lane = tid & 31;
    const int wm = wid >> 2, wn = wid & 3;
    const int row0 = blockIdx.y * SIM_BM, col0 = blockIdx.x * SIM_BM;

    MmaCtx cx;
    mma_mainloop_lin<NT>(Xhi + (size_t)row0 * D_DIM, Xlo + (size_t)row0 * D_DIM,
                         Whi + (size_t)col0 * D_DIM, Wlo + (size_t)col0 * D_DIM,
                         sb, tid, wm, wn, lane, cx);

    #pragma unroll
    for (int mi = 0; mi < 4; mi++) {
        int r = row0 + wm * 64 + mi * 16 + (lane >> 2);
        float rs0 = 0.f, rs1 = 0.f;
        #pragma unroll
        for (int nj = 0; nj < 4; nj++) {
            int c = col0 + wn * 32 + nj * 8 + (lane & 3) * 2;
            float b0 = bias[c], b1 = bias[c + 1];
            float z0 = cx.acc[mi][nj][0] + b0, z1 = cx.acc[mi][nj][1] + b1;
            float z2 = cx.acc[mi][nj][2] + b0, z3 = cx.acc[mi][nj][3] + b1;
            z0 = (z0 > 0.f) ? z0 : expm1f(z0);
            z1 = (z1 > 0.f) ? z1 : expm1f(z1);
            z2 = (z2 > 0.f) ? z2 : expm1f(z2);
            z3 = (z3 > 0.f) ? z3 : expm1f(z3);
            rs0 += z0 + z1;
            rs1 += z2 + z3;
            *reinterpret_cast<float2*>(Cout + (size_t)r * D_DIM + c) = make_float2(z0, z1);
            *reinterpret_cast<float2*>(Cout + (size_t)(r + 8) * D_DIM + c) = make_float2(z2, z3);
        }
        if (rowsum) {
            rs0 += __shfl_xor_sync(0xffffffffu, rs0, 1);
            rs0 += __shfl_xor_sync(0xffffffffu, rs0, 2);
            rs1 += __shfl_xor_sync(0xffffffffu, rs1, 1);
            rs1 += __shfl_xor_sync(0xffffffffu, rs1, 2);
            if ((lane & 3) == 0) {
                atomicAdd(rowsum + r, rs0);
                atomicAdd(rowsum + r + 8, rs1);
            }
        }
    }
}

// ==================== similarity: relu(emb @ emb^T), symmetric =============
__global__ __launch_bounds__(256, 2)
void sim_mma_kernel(const __half* __restrict__ emb,
                    float* __restrict__ out) {
    extern __shared__ char smem[];
    const uint32_t sb = smem_u32(smem);
    const int tid = threadIdx.x;
    const int wid = tid >> 5, lane = tid & 31;
    const int wm = wid >> 2, wn = wid & 3;

    int k = blockIdx.x;
    int bi = (int)((sqrtf(8.f * (float)k + 1.f) - 1.f) * 0.5f);
    while ((bi + 1) * (bi + 2) / 2 <= k) bi++;
    while (bi * (bi + 1) / 2 > k) bi--;
    int bj = k - bi * (bi + 1) / 2;
    const int row0 = bi * SIM_BM, col0 = bj * SIM_BM;

    MmaCtx cx;
    mma_mainloop_sim(emb + (size_t)row0 * D_DIM, emb + (size_t)col0 * D_DIM,
                     sb, tid, wm, wn, lane, cx);

    __syncthreads();
    float* Csm = reinterpret_cast<float*>(smem);   // 128 x 129 floats
    #pragma unroll
    for (int mi = 0; mi < 4; mi++) {
        int r = wm * 64 + mi * 16 + (lane >> 2);
        #pragma unroll
        for (int nj = 0; nj < 4; nj++) {
            int cc = wn * 32 + nj * 8 + (lane & 3) * 2;
            float z0 = cx.acc[mi][nj][0], z1 = cx.acc[mi][nj][1];
            float z2 = cx.acc[mi][nj][2], z3 = cx.acc[mi][nj][3];
            Csm[r * 129 + cc]           = (z0 > 0.f) ? z0 : 0.f;
            Csm[r * 129 + cc + 1]       = (z1 > 0.f) ? z1 : 0.f;
            Csm[(r + 8) * 129 + cc]     = (z2 > 0.f) ? z2 : 0.f;
            Csm[(r + 8) * 129 + cc + 1] = (z3 > 0.f) ? z3 : 0.f;
        }
    }
    __syncthreads();

    #pragma unroll 4
    for (int i = 0; i < 64; i++) {
        int idx = i * 256 + tid;
        int r = idx >> 7, cc = idx & 127;
        out[(size_t)(row0 + r) * N_NODES + col0 + cc] = Csm[r * 129 + cc];
    }
    if (bi != bj) {
        #pragma unroll 4
        for (int i = 0; i < 64; i++) {
            int idx = i * 256 + tid;
            int rr = idx & 127, cc = idx >> 7;
            out[(size_t)(col0 + cc) * N_NODES + row0 + rr] = Csm[rr * 129 + cc];
        }
    }
}

// ===========================================================================
extern "C" void kernel_launch(void* const* d_in, const int* in_sizes, int n_in,
                              void* d_out, int out_size) {
    const float* x  = (const float*)d_in[0];
    const int*   ei = (const int*)d_in[1];
    const float* ew = (const float*)d_in[2];
    const float* W  = (const float*)d_in[3];
    const float* b  = (const float*)d_in[4];
    float* out = (float*)d_out;

    float *A, *C, *rowsum, *csr_w;
    __half *y, *hi, *lo, *Whi, *Wlo;
    int *cnt, *csr_src;
    cudaGetSymbolAddress((void**)&A, g_bufA);
    cudaGetSymbolAddress((void**)&C, g_bufC);
    cudaGetSymbolAddress((void**)&y, g_y);
    cudaGetSymbolAddress((void**)&rowsum, g_rowsum);
    cudaGetSymbolAddress((void**)&hi, g_hi);
    cudaGetSymbolAddress((void**)&lo, g_lo);
    cudaGetSymbolAddress((void**)&Whi, g_Whi);
    cudaGetSymbolAddress((void**)&Wlo, g_Wlo);
    cudaGetSymbolAddress((void**)&cnt, g_cnt);
    cudaGetSymbolAddress((void**)&csr_src, g_csr_src);
    cudaGetSymbolAddress((void**)&csr_w, g_csr_w);

    cudaFuncSetAttribute(sim_mma_kernel,
                         cudaFuncAttributeMaxDynamicSharedMemorySize, SIM_SMEM_TOT);
    cudaFuncSetAttribute(lin_mma_kernel<3>,
                         cudaFuncAttributeMaxDynamicSharedMemorySize, LIN_SMEM3);
    cudaFuncSetAttribute(lin_mma_kernel<2>,
                         cudaFuncAttributeMaxDynamicSharedMemorySize, LIN_SMEM2);

    dim3 gLin(D_DIM / SIM_BM, N_NODES / SIM_BM);   // 4 x 64

    // ---- one-time per launch: zero, W split, bucketed CSR (one pass) ----
    zero2_kernel<<<N_NODES / 256, 256>>>(cnt, rowsum);
    wsplit_kernel<<<128, 256>>>(W, Whi, Wlo, D_DIM * D_DIM / 4);
    fill_bucket_kernel<<<E_EDGES / 512, 512>>>(ei, ew, cnt, csr_src, csr_w);

    // ---- layer 1: y = x*inv (fp16), gather y, lin 3-term (+fused rowsum) --
    rowsum_inv_y_kernel<<<N_NODES, 128>>>(x, y);
    spmm_csr_kernel<<<N_NODES, 128>>>(y, cnt, csr_src, csr_w, hi, lo);
    lin_mma_kernel<3><<<gLin, 256, LIN_SMEM3>>>(hi, lo, Whi, Wlo, b, C, rowsum);

    // ---- layer 2: y = C*inv (fp16), gather y, lin 2-term ----
    scale_y_kernel<<<N_NODES, 128>>>(C, rowsum, y);
    spmm_csr_kernel<<<N_NODES, 128>>>(y, cnt, csr_src, csr_w, hi, lo);
    lin_mma_kernel<2><<<gLin, 256, LIN_SMEM2>>>(hi, lo, Whi, Wlo, b, A, nullptr);

    // ---- normalize -> fp16 emb (reuse hi buffer) ----
    l2norm_f16_kernel<<<N_NODES, 128>>>(A, hi);

    // ---- similarity: symmetric tiles, pure fp16 + relu ----
    int nblk = (N_NODES / SIM_BM);             // 64
    int ntri = nblk * (nblk + 1) / 2;          // 2080
    sim_mma_kernel<<<ntri, 256, SIM_SMEM_TOT>>>(hi, out);
}

// round 17
// speedup vs baseline: 1.0580x; 1.0135x over previous
#include <cuda_runtime.h>
#include <cuda_fp16.h>
#include <math.h>
#include <stdint.h>

#define N_NODES 8192
#define D_DIM   512
#define E_EDGES 262144
#define BUCKET  128

// Scratch (allocation-free rule: device globals)
__device__ float g_bufA[N_NODES * D_DIM];  // layer-2 output / emb (f32)
__device__ float g_bufC[N_NODES * D_DIM];  // layer-1 output (f32)
__device__ __half g_y[N_NODES * D_DIM];    // fp16 pre-scaled gather source
__device__ float g_rowsum[N_NODES];        // fused rowsum accumulator
__device__ __half g_hi[N_NODES * D_DIM];   // fp16 hi (lin X) / fp16 emb (sim)
__device__ __half g_lo[N_NODES * D_DIM];   // fp16 lo (lin X)
__device__ __half g_Whi[D_DIM * D_DIM];    // W fp16 hi
__device__ __half g_Wlo[D_DIM * D_DIM];    // W fp16 lo (residual)
// bucketed CSR scratch
__device__ int   g_cnt[N_NODES];
__device__ int   g_csr_src[N_NODES * BUCKET];
__device__ float g_csr_w[N_NODES * BUCKET];

// ============================ PTX helpers (base PTX only!) =================
__device__ __forceinline__ uint32_t smem_u32(const void* p) {
    uint32_t a;
    asm("{ .reg .u64 t; cvta.to.shared.u64 t, %1; cvt.u32.u64 %0, t; }"
        : "=r"(a) : "l"(p));
    return a;
}
#define CPA16(s, g) \
    asm volatile("cp.async.cg.shared.global [%0], [%1], 16;" :: "r"(s), "l"(g))
#define CPA_COMMIT() asm volatile("cp.async.commit_group;" ::: "memory")

__device__ __forceinline__ void ldm_x4(uint32_t* r, uint32_t addr) {
    asm volatile("ldmatrix.sync.aligned.m8n8.x4.shared.b16 {%0,%1,%2,%3}, [%4];"
                 : "=r"(r[0]), "=r"(r[1]), "=r"(r[2]), "=r"(r[3]) : "r"(addr));
}
__device__ __forceinline__ void mma_fp16(float* c, const uint32_t* a,
                                         const uint32_t* b) {
    asm volatile(
        "mma.sync.aligned.m16n8k16.row.col.f32.f16.f16.f32 "
        "{%0,%1,%2,%3}, {%4,%5,%6,%7}, {%8,%9}, {%0,%1,%2,%3};"
        : "+f"(c[0]), "+f"(c[1]), "+f"(c[2]), "+f"(c[3])
        : "r"(a[0]), "r"(a[1]), "r"(a[2]), "r"(a[3]), "r"(b[0]), "r"(b[1]));
}
__device__ __forceinline__ void stcs(float* p, float v) {
    asm volatile("st.global.cs.f32 [%0], %1;" :: "l"(p), "f"(v) : "memory");
}

// ============================ small kernels ================================
// rowsum -> y = x * (1/(rowsum+1e-4)) in fp16 (rounded AFTER amplification)
__global__ void rowsum_inv_y_kernel(const float* __restrict__ x,
                                    __half* __restrict__ y) {
    int row = blockIdx.x;
    const float4 v = reinterpret_cast<const float4*>(x)[row * (D_DIM / 4) + threadIdx.x];
    float s = v.x + v.y + v.z + v.w;
    #pragma unroll
    for (int o = 16; o > 0; o >>= 1) s += __shfl_down_sync(0xffffffffu, s, o);
    __shared__ float red[4];
    __shared__ float sinv;
    if ((threadIdx.x & 31) == 0) red[threadIdx.x >> 5] = s;
    __syncthreads();
    if (threadIdx.x == 0) {
        float t = red[0] + red[1] + red[2] + red[3];
        sinv = 1.0f / (t + 1e-4f);
    }
    __syncthreads();
    float iv = sinv;
    int i = row * (D_DIM / 4) + threadIdx.x;
    reinterpret_cast<__half2*>(y)[i * 2]     = __floats2half2_rn(v.x * iv, v.y * iv);
    reinterpret_cast<__half2*>(y)[i * 2 + 1] = __floats2half2_rn(v.z * iv, v.w * iv);
}

// y = C * (1/(rowsum[row]+1e-4)) in fp16 (layer-2 message payload)
__global__ void scale_y_kernel(const float* __restrict__ C,
                               const float* __restrict__ rowsum,
                               __half* __restrict__ y) {
    int row = blockIdx.x;
    float iv = 1.0f / (rowsum[row] + 1e-4f);
    const float4 v = reinterpret_cast<const float4*>(C)[row * (D_DIM / 4) + threadIdx.x];
    int i = row * (D_DIM / 4) + threadIdx.x;
    reinterpret_cast<__half2*>(y)[i * 2]     = __floats2half2_rn(v.x * iv, v.y * iv);
    reinterpret_cast<__half2*>(y)[i * 2 + 1] = __floats2half2_rn(v.z * iv, v.w * iv);
}

__global__ void zero2_kernel(int* __restrict__ cnt, float* __restrict__ rowsum) {
    int i = blockIdx.x * blockDim.x + threadIdx.x;
    if (i < N_NODES) { cnt[i] = 0; rowsum[i] = 0.f; }
}

// merged: blocks [0,512) fill edge buckets; blocks [512,640) split W to fp16
__global__ void fill_and_wsplit_kernel(const int* __restrict__ ei,
                                       const float* __restrict__ ew,
                                       int* __restrict__ cnt,
                                       int* __restrict__ csr_src,
                                       float* __restrict__ csr_w,
                                       const float* __restrict__ W,
                                       __half* __restrict__ Whi,
                                       __half* __restrict__ Wlo) {
    if (blockIdx.x < 512) {
        int e = blockIdx.x * 512 + threadIdx.x;
        if (e >= E_EDGES) return;
        int dst = ei[e];
        int pos = atomicAdd(&cnt[dst], 1);
        if (pos < BUCKET) {
            csr_src[dst * BUCKET + pos] = ei[E_EDGES + e];
            csr_w[dst * BUCKET + pos] = ew[e];
        }
    } else {
        int i = (blockIdx.x - 512) * 512 + threadIdx.x;   // 65536 float4 chunks
        float4 v = reinterpret_cast<const float4*>(W)[i];
        float a[4] = {v.x, v.y, v.z, v.w};
        __half h[4], l[4];
        #pragma unroll
        for (int q = 0; q < 4; q++) {
            h[q] = __float2half_rn(a[q]);
            l[q] = __float2half_rn(a[q] - __half2float(h[q]));
        }
        reinterpret_cast<__half2*>(Whi)[i * 2]     = __halves2half2(h[0], h[1]);
        reinterpret_cast<__half2*>(Whi)[i * 2 + 1] = __halves2half2(h[2], h[3]);
        reinterpret_cast<__half2*>(Wlo)[i * 2]     = __halves2half2(l[0], l[1]);
        reinterpret_cast<__half2*>(Wlo)[i * 2 + 1] = __halves2half2(l[2], l[3]);
    }
}

// == bucket SpMM (fp16 gather, smem-staged indices) + fused fp16 hi/lo split =
__global__ __launch_bounds__(128)
void spmm_csr_kernel(const __half* __restrict__ y,
                     const int* __restrict__ cnt,
                     const int* __restrict__ csr_src, const float* __restrict__ csr_w,
                     __half* __restrict__ hi, __half* __restrict__ lo) {
    __shared__ int   s_src[BUCKET];
    __shared__ float s_w[BUCKET];
    int row = blockIdx.x;
    int t = threadIdx.x;
    int n = min(cnt[row], BUCKET);
    float acc[4] = {0.f, 0.f, 0.f, 0.f};

    if (t < n) {
        s_src[t] = csr_src[row * BUCKET + t];
        s_w[t] = csr_w[row * BUCKET + t];
    }
    __syncthreads();

    int j = 0;
    for (; j + 8 <= n; j += 8) {
        int idx8[8]; float w8[8]; uint2 p8[8];
        #pragma unroll
        for (int q = 0; q < 8; q++) { idx8[q] = s_src[j + q]; w8[q] = s_w[j + q]; }
        #pragma unroll
        for (int q = 0; q < 8; q++)
            p8[q] = __ldg(reinterpret_cast<const uint2*>(y) + idx8[q] * (D_DIM / 4) + t);
        #pragma unroll
        for (int q = 0; q < 8; q++) {
            float2 f;
            f = __half22float2(*reinterpret_cast<__half2*>(&p8[q].x));
            acc[0] = fmaf(w8[q], f.x, acc[0]); acc[1] = fmaf(w8[q], f.y, acc[1]);
            f = __half22float2(*reinterpret_cast<__half2*>(&p8[q].y));
            acc[2] = fmaf(w8[q], f.x, acc[2]); acc[3] = fmaf(w8[q], f.y, acc[3]);
        }
    }
    for (; j < n; j++) {
        int src = s_src[j];
        float w = s_w[j];
        uint2 p = __ldg(reinterpret_cast<const uint2*>(y) + src * (D_DIM / 4) + t);
        float2 f;
        f = __half22float2(*reinterpret_cast<__half2*>(&p.x));
        acc[0] = fmaf(w, f.x, acc[0]); acc[1] = fmaf(w, f.y, acc[1]);
        f = __half22float2(*reinterpret_cast<__half2*>(&p.y));
        acc[2] = fmaf(w, f.x, acc[2]); acc[3] = fmaf(w, f.y, acc[3]);
    }

    // fp16 hi/lo split of the f32 accumulator
    uint16_t h[4], l[4];
    #pragma unroll
    for (int q = 0; q < 4; q++) {
        __half hb = __float2half_rn(acc[q]);
        __half lb = __float2half_rn(acc[q] - __half2float(hb));
        h[q] = *reinterpret_cast<uint16_t*>(&hb);
        l[q] = *reinterpret_cast<uint16_t*>(&lb);
    }
    int i = row * (D_DIM / 4) + t;
    reinterpret_cast<uint2*>(hi)[i] =
        make_uint2(((uint32_t)h[1] << 16) | h[0], ((uint32_t)h[3] << 16) | h[2]);
    reinterpret_cast<uint2*>(lo)[i] =
        make_uint2(((uint32_t)l[1] << 16) | l[0], ((uint32_t)l[3] << 16) | l[2]);
}

// L2 normalize rows of x and emit fp16
__global__ void l2norm_f16_kernel(const float* __restrict__ x,
                                  __half* __restrict__ emb) {
    int row = blockIdx.x;
    const float4 v = reinterpret_cast<const float4*>(x)[row * (D_DIM / 4) + threadIdx.x];
    float s = v.x * v.x + v.y * v.y + v.z * v.z + v.w * v.w;
    #pragma unroll
    for (int o = 16; o > 0; o >>= 1) s += __shfl_down_sync(0xffffffffu, s, o);
    __shared__ float red[4];
    __shared__ float sscale;
    if ((threadIdx.x & 31) == 0) red[threadIdx.x >> 5] = s;
    __syncthreads();
    if (threadIdx.x == 0) {
        float t = red[0] + red[1] + red[2] + red[3];
        sscale = 1.0f / fmaxf(sqrtf(t), 1e-12f);
    }
    __syncthreads();
    float sc = sscale;
    int i = row * (D_DIM / 4) + threadIdx.x;
    reinterpret_cast<__half2*>(emb)[i * 2]     = __floats2half2_rn(v.x * sc, v.y * sc);
    reinterpret_cast<__half2*>(emb)[i * 2 + 1] = __floats2half2_rn(v.z * sc, v.w * sc);
}

// ==================== shared mma tile machinery (128x128) ==================
#define SIM_BM 128
#define SIM_KC 32
#define ROWB   80
#define OPSZ   (SIM_BM * ROWB)          // 10240 B
#define LIN_STG2 (3 * OPSZ)             // Xhi, Xlo, Whi: 30720 B
#define LIN_STG3 (4 * OPSZ)             // + Wlo: 40960 B
#define LIN_SMEM2 (2 * LIN_STG2)        // 61440 B
#define LIN_SMEM3 (2 * LIN_STG3)        // 81920 B
#define SIM_STG  (2 * OPSZ)             // 20480 B
#define SIM_NSTG 3
#define SIM_SMEM_TOT (SIM_BM * 129 * 4) // 66048 B (>= 3*SIM_STG = 61440)
#define NCHUNK (D_DIM / SIM_KC)

struct MmaCtx { float acc[4][4][4]; };

// fp16 lin mainloop: acc = (Xhi+Xlo) x Whi^T [+ Xhi x Wlo^T if NT==3], 2-stage
template <int NT>
__device__ __forceinline__ void mma_mainloop_lin(
    const __half* gA0, const __half* gA1,
    const __half* gB0, const __half* gB1,
    uint32_t sb, int tid, int wm, int wn, int lane, MmaCtx& cx) {

    const int STG = (NT == 3) ? LIN_STG3 : LIN_STG2;

    #pragma unroll
    for (int i = 0; i < 4; i++)
        #pragma unroll
        for (int j = 0; j < 4; j++)
            #pragma unroll
            for (int q = 0; q < 4; q++) cx.acc[i][j][q] = 0.f;

    const __half* gA[2] = {gA0, gA1};

    auto load_chunk = [&](int c) {
        uint32_t st = sb + (uint32_t)(c & 1) * STG;
        int koff = c * SIM_KC;
        #pragma unroll
        for (int i = 0; i < 2; i++) {
            int idx = i * 256 + tid;
            int r = idx >> 2, cc = idx & 3;
            #pragma unroll
            for (int h = 0; h < 2; h++)
                CPA16(st + h * OPSZ + r * ROWB + cc * 16,
                      gA[h] + (size_t)r * D_DIM + koff + cc * 8);
            CPA16(st + 2 * OPSZ + r * ROWB + cc * 16,
                  gB0 + (size_t)r * D_DIM + koff + cc * 8);
            if (NT == 3)
                CPA16(st + 3 * OPSZ + r * ROWB + cc * 16,
                      gB1 + (size_t)r * D_DIM + koff + cc * 8);
        }
        CPA_COMMIT();
    };

    load_chunk(0);
    load_chunk(1);

    for (int c = 0; c < NCHUNK; c++) {
        if (c < NCHUNK - 1) asm volatile("cp.async.wait_group 1;" ::: "memory");
        else                asm volatile("cp.async.wait_group 0;" ::: "memory");
        __syncthreads();

        uint32_t st = sb + (uint32_t)(c & 1) * STG;
        #pragma unroll
        for (int ks = 0; ks < 2; ks++) {
            uint32_t afr[2][4][4];
            {
                int rowA = wm * 64 + (lane & 15);
                int chk = 2 * ks + (lane >> 4);
                uint32_t off = (uint32_t)(rowA * ROWB + chk * 16);
                #pragma unroll
                for (int h = 0; h < 2; h++)
                    #pragma unroll
                    for (int mi = 0; mi < 4; mi++)
                        ldm_x4(afr[h][mi], st + h * OPSZ + off + (uint32_t)(mi * 16 * ROWB));
            }
            uint32_t bfr[4][2], cfr[4][2];
            {
                int rowB = wn * 32 + ((lane >> 4) & 1) * 8 + (lane & 7);
                int chk = 2 * ks + ((lane >> 3) & 1);
                uint32_t off = (uint32_t)(rowB * ROWB + chk * 16);
                #pragma unroll
                for (int jp = 0; jp < 2; jp++) {
                    uint32_t r4[4];
                    ldm_x4(r4, st + 2 * OPSZ + off + (uint32_t)(jp * 16 * ROWB));
                    bfr[jp * 2 + 0][0] = r4[0]; bfr[jp * 2 + 0][1] = r4[1];
                    bfr[jp * 2 + 1][0] = r4[2]; bfr[jp * 2 + 1][1] = r4[3];
                    if (NT == 3) {
                        ldm_x4(r4, st + 3 * OPSZ + off + (uint32_t)(jp * 16 * ROWB));
                        cfr[jp * 2 + 0][0] = r4[0]; cfr[jp * 2 + 0][1] = r4[1];
                        cfr[jp * 2 + 1][0] = r4[2]; cfr[jp * 2 + 1][1] = r4[3];
                    }
                }
            }
            #pragma unroll
            for (int mi = 0; mi < 4; mi++)
                #pragma unroll
                for (int nj = 0; nj < 4; nj++) {
                    mma_fp16(cx.acc[mi][nj], afr[0][mi], bfr[nj]);      // Xhi*Whi
                    mma_fp16(cx.acc[mi][nj], afr[1][mi], bfr[nj]);      // Xlo*Whi
                    if (NT == 3)
                        mma_fp16(cx.acc[mi][nj], afr[0][mi], cfr[nj]);  // Xhi*Wlo
                }
        }
        __syncthreads();
        if (c + 2 < NCHUNK) load_chunk(c + 2);
    }
}

// fp16 1-term mainloop (similarity): acc = embA x embB^T, 3-stage
__device__ __forceinline__ void mma_mainloop_sim(
    const __half* gA0, const __half* gB0,
    uint32_t sb, int tid, int wm, int wn, int lane, MmaCtx& cx) {

    #pragma unroll
    for (int i = 0; i < 4; i++)
        #pragma unroll
        for (int j = 0; j < 4; j++)
            #pragma unroll
            for (int q = 0; q < 4; q++) cx.acc[i][j][q] = 0.f;

    auto load_chunk = [&](int c) {
        uint32_t st = sb + (uint32_t)(c % SIM_NSTG) * SIM_STG;
        int koff = c * SIM_KC;
        #pragma unroll
        for (int i = 0; i < 2; i++) {
            int idx = i * 256 + tid;
            int r = idx >> 2, cc = idx & 3;
            CPA16(st + r * ROWB + cc * 16,
                  gA0 + (size_t)r * D_DIM + koff + cc * 8);
            CPA16(st + OPSZ + r * ROWB + cc * 16,
                  gB0 + (size_t)r * D_DIM + koff + cc * 8);
        }
        CPA_COMMIT();
    };

    load_chunk(0);
    load_chunk(1);
    load_chunk(2);

    for (int c = 0; c < NCHUNK; c++) {
        if (c + 2 < NCHUNK)      asm volatile("cp.async.wait_group 2;" ::: "memory");
        else if (c + 1 < NCHUNK) asm volatile("cp.async.wait_group 1;" ::: "memory");
        else                     asm volatile("cp.async.wait_group 0;" ::: "memory");
        __syncthreads();

        uint32_t st = sb + (uint32_t)(c % SIM_NSTG) * SIM_STG;
        #pragma unroll
        for (int ks = 0; ks < 2; ks++) {
            uint32_t afr[4][4];
            {
                int rowA = wm * 64 + (lane & 15);
                int chk = 2 * ks + (lane >> 4);
                uint32_t off = (uint32_t)(rowA * ROWB + chk * 16);
                #pragma unroll
                for (int mi = 0; mi < 4; mi++)
                    ldm_x4(afr[mi], st + off + (uint32_t)(mi * 16 * ROWB));
            }
            uint32_t bfr[4][2];
            {
                int rowB = wn * 32 + ((lane >> 4) & 1) * 8 + (lane & 7);
                int chk = 2 * ks + ((lane >> 3) & 1);
                uint32_t off = (uint32_t)(rowB * ROWB + chk * 16);
                #pragma unroll
                for (int jp = 0; jp < 2; jp++) {
                    uint32_t r4[4];
                    ldm_x4(r4, st + OPSZ + off + (uint32_t)(jp * 16 * ROWB));
                    bfr[jp * 2 + 0][0] = r4[0]; bfr[jp * 2 + 0][1] = r4[1];
                    bfr[jp * 2 + 1][0] = r4[2]; bfr[jp * 2 + 1][1] = r4[3];
                }
            }
            #pragma unroll
            for (int mi = 0; mi < 4; mi++)
                #pragma unroll
                for (int nj = 0; nj < 4; nj++)
                    mma_fp16(cx.acc[mi][nj], afr[mi], bfr[nj]);
        }
        __syncthreads();
        if (c + 3 < NCHUNK) load_chunk(c + 3);
    }
}

// ==================== linear layer: elu(X @ W^T + b) [+ rowsum] ============
template <int NT>
__global__ __launch_bounds__(256, 2)
void lin_mma_kernel(const __half* __restrict__ Xhi,
                    const __half* __restrict__ Xlo,
                    const __half* __restrict__ Whi,
                    const __half* __restrict__ Wlo,
                    const float* __restrict__ bias,
                    float* __restrict__ Cout,
                    float* __restrict__ rowsum) {
    extern __shared__ char smem[];
    const uint32_t sb = smem_u32(smem);
    const int tid = threadIdx.x;
    const int wid = tid >> 5, lane = tid & 31;
    const int wm = wid >> 2, wn = wid & 3;
    const int row0 = blockIdx.y * SIM_BM, col0 = blockIdx.x * SIM_BM;

    MmaCtx cx;
    mma_mainloop_lin<NT>(Xhi + (size_t)row0 * D_DIM, Xlo + (size_t)row0 * D_DIM,
                         Whi + (size_t)col0 * D_DIM, Wlo + (size_t)col0 * D_DIM,
                         sb, tid, wm, wn, lane, cx);

    #pragma unroll
    for (int mi = 0; mi < 4; mi++) {
        int r = row0 + wm * 64 + mi * 16 + (lane >> 2);
        float rs0 = 0.f, rs1 = 0.f;
        #pragma unroll
        for (int nj = 0; nj < 4; nj++) {
            int c = col0 + wn * 32 + nj * 8 + (lane & 3) * 2;
            float b0 = bias[c], b1 = bias[c + 1];
            float z0 = cx.acc[mi][nj][0] + b0, z1 = cx.acc[mi][nj][1] + b1;
            float z2 = cx.acc[mi][nj][2] + b0, z3 = cx.acc[mi][nj][3] + b1;
            z0 = (z0 > 0.f) ? z0 : expm1f(z0);
            z1 = (z1 > 0.f) ? z1 : expm1f(z1);
            z2 = (z2 > 0.f) ? z2 : expm1f(z2);
            z3 = (z3 > 0.f) ? z3 : expm1f(z3);
            rs0 += z0 + z1;
            rs1 += z2 + z3;
            *reinterpret_cast<float2*>(Cout + (size_t)r * D_DIM + c) = make_float2(z0, z1);
            *reinterpret_cast<float2*>(Cout + (size_t)(r + 8) * D_DIM + c) = make_float2(z2, z3);
        }
        if (rowsum) {
            rs0 += __shfl_xor_sync(0xffffffffu, rs0, 1);
            rs0 += __shfl_xor_sync(0xffffffffu, rs0, 2);
            rs1 += __shfl_xor_sync(0xffffffffu, rs1, 1);
            rs1 += __shfl_xor_sync(0xffffffffu, rs1, 2);
            if ((lane & 3) == 0) {
                atomicAdd(rowsum + r, rs0);
                atomicAdd(rowsum + r + 8, rs1);
            }
        }
    }
}

// ==================== similarity: relu(emb @ emb^T), symmetric =============
__global__ __launch_bounds__(256, 2)
void sim_mma_kernel(const __half* __restrict__ emb,
                    float* __restrict__ out) {
    extern __shared__ char smem[];
    const uint32_t sb = smem_u32(smem);
    const int tid = threadIdx.x;
    const int wid = tid >> 5, lane = tid & 31;
    const int wm = wid >> 2, wn = wid & 3;

    int k = blockIdx.x;
    int bi = (int)((sqrtf(8.f * (float)k + 1.f) - 1.f) * 0.5f);
    while ((bi + 1) * (bi + 2) / 2 <= k) bi++;
    while (bi * (bi + 1) / 2 > k) bi--;
    int bj = k - bi * (bi + 1) / 2;
    const int row0 = bi * SIM_BM, col0 = bj * SIM_BM;

    MmaCtx cx;
    mma_mainloop_sim(emb + (size_t)row0 * D_DIM, emb + (size_t)col0 * D_DIM,
                     sb, tid, wm, wn, lane, cx);

    __syncthreads();
    float* Csm = reinterpret_cast<float*>(smem);   // 128 x 129 floats
    #pragma unroll
    for (int mi = 0; mi < 4; mi++) {
        int r = wm * 64 + mi * 16 + (lane >> 2);
        #pragma unroll
        for (int nj = 0; nj < 4; nj++) {
            int cc = wn * 32 + nj * 8 + (lane & 3) * 2;
            float z0 = cx.acc[mi][nj][0], z1 = cx.acc[mi][nj][1];
            float z2 = cx.acc[mi][nj][2], z3 = cx.acc[mi][nj][3];
            Csm[r * 129 + cc]           = (z0 > 0.f) ? z0 : 0.f;
            Csm[r * 129 + cc + 1]       = (z1 > 0.f) ? z1 : 0.f;
            Csm[(r + 8) * 129 + cc]     = (z2 > 0.f) ? z2 : 0.f;
            Csm[(r + 8) * 129 + cc + 1] = (z3 > 0.f) ? z3 : 0.f;
        }
    }
    __syncthreads();

    // streaming stores: out is write-once, keep L2 for emb/stage tiles
    #pragma unroll 4
    for (int i = 0; i < 64; i++) {
        int idx = i * 256 + tid;
        int r = idx >> 7, cc = idx & 127;
        stcs(out + (size_t)(row0 + r) * N_NODES + col0 + cc, Csm[r * 129 + cc]);
    }
    if (bi != bj) {
        #pragma unroll 4
        for (int i = 0; i < 64; i++) {
            int idx = i * 256 + tid;
            int rr = idx & 127, cc = idx >> 7;
            stcs(out + (size_t)(col0 + cc) * N_NODES + row0 + rr, Csm[rr * 129 + cc]);
        }
    }
}

// ===========================================================================
extern "C" void kernel_launch(void* const* d_in, const int* in_sizes, int n_in,
                              void* d_out, int out_size) {
    const float* x  = (const float*)d_in[0];
    const int*   ei = (const int*)d_in[1];
    const float* ew = (const float*)d_in[2];
    const float* W  = (const float*)d_in[3];
    const float* b  = (const float*)d_in[4];
    float* out = (float*)d_out;

    float *A, *C, *rowsum, *csr_w;
    __half *y, *hi, *lo, *Whi, *Wlo;
    int *cnt, *csr_src;
    cudaGetSymbolAddress((void**)&A, g_bufA);
    cudaGetSymbolAddress((void**)&C, g_bufC);
    cudaGetSymbolAddress((void**)&y, g_y);
    cudaGetSymbolAddress((void**)&rowsum, g_rowsum);
    cudaGetSymbolAddress((void**)&hi, g_hi);
    cudaGetSymbolAddress((void**)&lo, g_lo);
    cudaGetSymbolAddress((void**)&Whi, g_Whi);
    cudaGetSymbolAddress((void**)&Wlo, g_Wlo);
    cudaGetSymbolAddress((void**)&cnt, g_cnt);
    cudaGetSymbolAddress((void**)&csr_src, g_csr_src);
    cudaGetSymbolAddress((void**)&csr_w, g_csr_w);

    cudaFuncSetAttribute(sim_mma_kernel,
                         cudaFuncAttributeMaxDynamicSharedMemorySize, SIM_SMEM_TOT);
    cudaFuncSetAttribute(lin_mma_kernel<3>,
                         cudaFuncAttributeMaxDynamicSharedMemorySize, LIN_SMEM3);
    cudaFuncSetAttribute(lin_mma_kernel<2>,
                         cudaFuncAttributeMaxDynamicSharedMemorySize, LIN_SMEM2);

    dim3 gLin(D_DIM / SIM_BM, N_NODES / SIM_BM);   // 4 x 64

    // ---- one-time per launch: zero; merged fill-bucket + W split ----
    zero2_kernel<<<N_NODES / 256, 256>>>(cnt, rowsum);
    fill_and_wsplit_kernel<<<512 + 128, 512>>>(ei, ew, cnt, csr_src, csr_w,
                                               W, Whi, Wlo);

    // ---- layer 1: y = x*inv (fp16), gather y, lin 3-term (+fused rowsum) --
    rowsum_inv_y_kernel<<<N_NODES, 128>>>(x, y);
    spmm_csr_kernel<<<N_NODES, 128>>>(y, cnt, csr_src, csr_w, hi, lo);
    lin_mma_kernel<3><<<gLin, 256, LIN_SMEM3>>>(hi, lo, Whi, Wlo, b, C, rowsum);

    // ---- layer 2: y = C*inv (fp16), gather y, lin 2-term ----
    scale_y_kernel<<<N_NODES, 128>>>(C, rowsum, y);
    spmm_csr_kernel<<<N_NODES, 128>>>(y, cnt, csr_src, csr_w, hi, lo);
    lin_mma_kernel<2><<<gLin, 256, LIN_SMEM2>>>(hi, lo, Whi, Wlo, b, A, nullptr);

    // ---- normalize -> fp16 emb (reuse hi buffer) ----
    l2norm_f16_kernel<<<N_NODES, 128>>>(A, hi);

    // ---- similarity: symmetric tiles, pure fp16 + relu, streaming stores --
    int nblk = (N_NODES / SIM_BM);             // 64
    int ntri = nblk * (nblk + 1) / 2;          // 2080
    sim_mma_kernel<<<ntri, 256, SIM_SMEM_TOT>>>(hi, out);
}